// round 7
// baseline (speedup 1.0000x reference)
#include <cuda_runtime.h>
#include <cuda_fp16.h>
#include <math.h>
#include <stdint.h>

// ---------------------------------------------------------------------------
// GCViT block, R7: f16 tensor-core GEMMs (256-thr blocks), half kv,
// proj+residual+LN2 fused (window-ordered), window-reverse in fc2 store.
// Shapes: B=32 H=W=64 C=192 NH=6 hd=32 WS=8 N=64 hidden=768
// ---------------------------------------------------------------------------

#define TOKENS   131072
#define CH       192
#define HIDDEN   768
#define NWIN     2048
#define WN_TOK   64
#define NHEADS   6
#define HD       32

__device__ __half g_hwin_h[TOKENS * CH];          // LN1 out, window order
__device__ __half g_kv_h [TOKENS * 2 * CH];       // KV, window order (half)
__device__ __half g_ow_h [TOKENS * CH];           // attn out, window order
__device__ float  g_y    [TOKENS * CH];           // residual-1, WINDOW order
__device__ __half g_h2_h [TOKENS * CH];           // LN2 out, WINDOW order
__device__ __half g_a1_h [TOKENS * HIDDEN];       // fc1 act, window order
// transposed half weights: qkv[384][192] | proj[192][192] | fc1[768][192] | fc2[192][768]
__device__ __half g_wt[73728 + 36864 + 147456 + 147456];

// window-order row -> original token index
__device__ __forceinline__ int win2orig(int w) {
    int bi = w >> 12, rem = w & 4095;
    int win = rem >> 6, pos = rem & 63;
    return (bi << 12) + ((((win >> 3) << 3) + (pos >> 3)) << 6)
         + ((win & 7) << 3) + (pos & 7);
}

__device__ __forceinline__ float warp_sum(float v) {
#pragma unroll
    for (int o = 16; o; o >>= 1) v += __shfl_xor_sync(0xffffffffu, v, o);
    return v;
}

// W[K][N] f32 -> Wt[N][K] half. block (32,8), grid (N/32, K/32)
__global__ void wconv_kernel(const float* __restrict__ W, __half* __restrict__ Wt,
                             int K, int N) {
    __shared__ float t[32][33];
    int k0 = blockIdx.y * 32, n0 = blockIdx.x * 32;
    int tx = threadIdx.x, ty = threadIdx.y;
#pragma unroll
    for (int i = 0; i < 32; i += 8)
        t[ty + i][tx] = W[(size_t)(k0 + ty + i) * N + n0 + tx];
    __syncthreads();
#pragma unroll
    for (int i = 0; i < 32; i += 8)
        Wt[(size_t)(n0 + ty + i) * K + k0 + tx] = __float2half(t[tx][ty + i]);
}

__global__ void ln1_win_kernel(const float* __restrict__ x,
                               const float* __restrict__ g,
                               const float* __restrict__ b,
                               __half* __restrict__ hw) {
    int tok  = (blockIdx.x * blockDim.x + threadIdx.x) >> 5;
    int lane = threadIdx.x & 31;
    const float* xr = x + (size_t)tok * CH;
    float v[6], s = 0.f, s2 = 0.f;
#pragma unroll
    for (int j = 0; j < 6; j++) {
        float t = xr[lane + 32 * j];
        v[j] = t; s += t; s2 += t * t;
    }
    s = warp_sum(s); s2 = warp_sum(s2);
    float mean = s * (1.f / CH);
    float var  = s2 * (1.f / CH) - mean * mean;
    float inv  = rsqrtf(var + 1e-5f);
    int bi = tok >> 12;
    int hh = (tok >> 6) & 63;
    int ww = tok & 63;
    size_t dst = ((size_t)(bi * 64 + ((hh >> 3) << 3) + (ww >> 3)) * WN_TOK
                  + ((hh & 7) << 3) + (ww & 7)) * CH;
#pragma unroll
    for (int j = 0; j < 6; j++) {
        int c = lane + 32 * j;
        hw[dst + c] = __float2half((v[j] - mean) * inv * g[c] + b[c]);
    }
}

// ---------------------------------------------------------------------------
// Attention: block = one (window, head); 64 threads, thread n = query row n.
// kv is half now.
// ---------------------------------------------------------------------------
__global__ void attn_kernel(const __half* __restrict__ kv,
                            const float* __restrict__ qg,
                            const float* __restrict__ rpb,
                            __half* __restrict__ ow) {
    __shared__ float ks[WN_TOK][HD];
    __shared__ float vs[WN_TOK][HD];
    __shared__ float ss[WN_TOK][WN_TOK + 1];
    __shared__ float bsh[225];

    const int head = blockIdx.x;
    const int wb   = blockIdx.y;
    const int tid  = threadIdx.x;
    const int bimg = wb >> 6;

    // K/V tiles: 64x32 halves each; 8-half (16B) chunks
    const __half* kvb = kv + (size_t)wb * WN_TOK * (2 * CH) + head * HD;
#pragma unroll
    for (int it = 0; it < 4; it++) {
        int i  = tid + it * 64;
        int m  = i >> 2;
        int d8 = (i & 3) * 8;
        uint4 kr = *(const uint4*)&kvb[(size_t)m * 384 + d8];
        uint4 vr = *(const uint4*)&kvb[(size_t)m * 384 + CH + d8];
        const __half2* kh = (const __half2*)&kr;
        const __half2* vh = (const __half2*)&vr;
#pragma unroll
        for (int j = 0; j < 4; j++) {
            float2 kf = __half22float2(kh[j]);
            float2 vf = __half22float2(vh[j]);
            ks[m][d8 + 2 * j]     = kf.x;
            ks[m][d8 + 2 * j + 1] = kf.y;
            vs[m][d8 + 2 * j]     = vf.x;
            vs[m][d8 + 2 * j + 1] = vf.y;
        }
    }
    for (int i = tid; i < 225; i += 64) bsh[i] = rpb[i * NHEADS + head];
    __syncthreads();

    float q[HD];
    const float* qr = qg + (((size_t)bimg * WN_TOK + tid) * NHEADS + head) * HD;
#pragma unroll
    for (int d = 0; d < HD; d++) q[d] = qr[d] * 0.17677669529663687f;

    const int ni = tid >> 3, nj = tid & 7;

    float mx = -1e30f;
#pragma unroll 8
    for (int m = 0; m < WN_TOK; m++) {
        float acc = 0.f;
#pragma unroll
        for (int d4 = 0; d4 < 8; d4++) {
            float4 kk = *(const float4*)&ks[m][d4 * 4];
            acc += q[d4 * 4 + 0] * kk.x + q[d4 * 4 + 1] * kk.y
                 + q[d4 * 4 + 2] * kk.z + q[d4 * 4 + 3] * kk.w;
        }
        int mi = m >> 3, mj = m & 7;
        acc += bsh[(ni - mi + 7) * 15 + (nj - mj + 7)];
        ss[tid][m] = acc;
        mx = fmaxf(mx, acc);
    }
    float sum = 0.f;
#pragma unroll 8
    for (int m = 0; m < WN_TOK; m++) {
        float e = expf(ss[tid][m] - mx);
        ss[tid][m] = e;
        sum += e;
    }
    const float inv = 1.f / sum;

    float ov[HD];
#pragma unroll
    for (int d = 0; d < HD; d++) ov[d] = 0.f;
#pragma unroll 8
    for (int m = 0; m < WN_TOK; m++) {
        float p = ss[tid][m] * inv;
#pragma unroll
        for (int d4 = 0; d4 < 8; d4++) {
            float4 vv = *(const float4*)&vs[m][d4 * 4];
            ov[d4 * 4 + 0] += p * vv.x;
            ov[d4 * 4 + 1] += p * vv.y;
            ov[d4 * 4 + 2] += p * vv.z;
            ov[d4 * 4 + 3] += p * vv.w;
        }
    }
    __half* orow = ow + ((size_t)wb * WN_TOK + tid) * CH + head * HD;
#pragma unroll
    for (int d2 = 0; d2 < 16; d2++)
        *(__half2*)(orow + d2 * 2) = __floats2half2_rn(ov[d2 * 2], ov[d2 * 2 + 1]);
}

// ---------------------------------------------------------------------------
// f16 MMA helpers
// ---------------------------------------------------------------------------
__device__ __forceinline__ void cp_async16(uint32_t d, const void* s) {
    asm volatile("cp.async.cg.shared.global [%0], [%1], 16;\n" :: "r"(d), "l"(s));
}
__device__ __forceinline__ void ldsm4(uint32_t* r, uint32_t addr) {
    asm volatile("ldmatrix.sync.aligned.m8n8.x4.shared.b16 {%0,%1,%2,%3}, [%4];\n"
                 : "=r"(r[0]), "=r"(r[1]), "=r"(r[2]), "=r"(r[3]) : "r"(addr));
}
__device__ __forceinline__ void mma_f16(float* c, const uint32_t* a, const uint32_t* b) {
    asm volatile(
        "mma.sync.aligned.m16n8k16.row.col.f32.f16.f16.f32 "
        "{%0,%1,%2,%3}, {%4,%5,%6,%7}, {%8,%9}, {%0,%1,%2,%3};\n"
        : "+f"(c[0]), "+f"(c[1]), "+f"(c[2]), "+f"(c[3])
        : "r"(a[0]), "r"(a[1]), "r"(a[2]), "r"(a[3]), "r"(b[0]), "r"(b[1]));
}

// ---------------------------------------------------------------------------
// 256-thread f16 GEMM: C[M,N] = A[M,K] @ Wt[N,K]^T + bias (+epilogue)
// BM=128, BN=64, BK=32, 3 stages. 8 warps (4m x 2n), warp tile 32x32.
// EPI: 1=bias+GELU->half  2=bias+residual(y)->f32 with window-reverse store
//      3=bias->half
// ---------------------------------------------------------------------------
template<int EPI>
__global__ void __launch_bounds__(256)
hgemm_kernel(const __half* __restrict__ Ag, const __half* __restrict__ Bt,
             const float* __restrict__ bias, const float* __restrict__ res,
             void* __restrict__ Cg, int N, int K) {
    constexpr int BM = 128, BN = 64, BK = 32, STG = 3;
    constexpr int STR = BK + 8;                 // 40 halves
    constexpr int AH = BM * STR;                // 5120
    constexpr int BH = BN * STR;                // 2560
    constexpr int STW = AH + BH;

    __shared__ __half sm[STW * STG];

    const int tid = threadIdx.x;
    const int w = tid >> 5, l = tid & 31;
    const int wm = w >> 1, wn = w & 1;

    const __half* Ab = Ag + (size_t)blockIdx.y * BM * K;
    const __half* Bb = Bt + (size_t)blockIdx.x * BN * K;
    const uint32_t smb = (uint32_t)__cvta_generic_to_shared(sm);

    const uint32_t a_off = (uint32_t)(((wm * 32 + (l & 15)) * STR + (l >> 4) * 8) * 2);
    const int n_off = (l & 7) + ((l >> 4) << 3);
    const int k_off = ((l >> 3) & 1) * 8;
    const uint32_t b_off = (uint32_t)((AH + (wn * 32 + n_off) * STR + k_off) * 2);

    float acc[2][4][4];
#pragma unroll
    for (int mt = 0; mt < 2; mt++)
#pragma unroll
        for (int nt = 0; nt < 4; nt++)
#pragma unroll
            for (int i = 0; i < 4; i++) acc[mt][nt][i] = 0.f;

    auto load = [&](int kc, int s) {
        uint32_t base = smb + (uint32_t)(s * STW) * 2u;
#pragma unroll
        for (int it = 0; it < 2; it++) {        // A: 128 rows x 4 chunks
            int i = tid + it * 256;
            int r = i >> 2, c4 = i & 3;
            cp_async16(base + (uint32_t)(r * STR + c4 * 8) * 2u,
                       Ab + (size_t)r * K + kc * BK + c4 * 8);
        }
        {                                       // B: 64 rows x 4 chunks
            int r = tid >> 2, c4 = tid & 3;
            cp_async16(base + (uint32_t)(AH + r * STR + c4 * 8) * 2u,
                       Bb + (size_t)r * K + kc * BK + c4 * 8);
        }
    };

    auto compute = [&](int s) {
        uint32_t stage = smb + (uint32_t)(s * STW) * 2u;
#pragma unroll
        for (int ks = 0; ks < 2; ks++) {
            uint32_t af[2][4], bf[4][2];
#pragma unroll
            for (int mt = 0; mt < 2; mt++)
                ldsm4(af[mt], stage + a_off + (uint32_t)((mt * 16 * STR + ks * 16) * 2));
#pragma unroll
            for (int ntp = 0; ntp < 2; ntp++) {
                uint32_t t4[4];
                ldsm4(t4, stage + b_off + (uint32_t)((ntp * 16 * STR + ks * 16) * 2));
                bf[ntp * 2 + 0][0] = t4[0]; bf[ntp * 2 + 0][1] = t4[1];
                bf[ntp * 2 + 1][0] = t4[2]; bf[ntp * 2 + 1][1] = t4[3];
            }
#pragma unroll
            for (int mt = 0; mt < 2; mt++)
#pragma unroll
                for (int nt = 0; nt < 4; nt++)
                    mma_f16(acc[mt][nt], af[mt], bf[nt]);
        }
    };

    const int CHUNKS = K / BK;
#pragma unroll
    for (int s = 0; s < STG - 1; s++) {
        load(s, s);
        asm volatile("cp.async.commit_group;\n" ::: "memory");
    }
    for (int c = 0; c < CHUNKS; c++) {
        asm volatile("cp.async.wait_group %0;\n" :: "n"(STG - 2) : "memory");
        __syncthreads();
        if (c + STG - 1 < CHUNKS) load(c + STG - 1, (c + STG - 1) % STG);
        asm volatile("cp.async.commit_group;\n" ::: "memory");
        compute(c % STG);
        __syncthreads();
    }

    const int row0 = blockIdx.y * BM + wm * 32 + (l >> 2);
    const int col0 = blockIdx.x * BN + wn * 32 + 2 * (l & 3);
#pragma unroll
    for (int mt = 0; mt < 2; mt++) {
#pragma unroll
        for (int h = 0; h < 2; h++) {
            int row = row0 + mt * 16 + h * 8;
#pragma unroll
            for (int nt = 0; nt < 4; nt++) {
                int col = col0 + nt * 8;
                float v0 = acc[mt][nt][h * 2 + 0] + bias[col];
                float v1 = acc[mt][nt][h * 2 + 1] + bias[col + 1];
                if (EPI == 1) {
                    v0 = 0.5f * v0 * (1.0f + erff(v0 * 0.70710678118654752f));
                    v1 = 0.5f * v1 * (1.0f + erff(v1 * 0.70710678118654752f));
                    *(__half2*)((__half*)Cg + (size_t)row * N + col) =
                        __floats2half2_rn(v0, v1);
                } else if (EPI == 3) {
                    *(__half2*)((__half*)Cg + (size_t)row * N + col) =
                        __floats2half2_rn(v0, v1);
                } else {  // EPI 2: +residual(y window-order), store window-reversed
                    v0 += res[(size_t)row * N + col];
                    v1 += res[(size_t)row * N + col + 1];
                    int orow = win2orig(row);
                    *(float2*)((float*)Cg + (size_t)orow * N + col) =
                        make_float2(v0, v1);
                }
            }
        }
    }
}

// ---------------------------------------------------------------------------
// Fused proj GEMM + residual + LN2.  BM=64, BN=192(full), BK=32, 3 stages.
// 256 threads, 8 warps (2m x 4n), warp tile 32x48.
// Inputs window-ordered; y (f32) and h2 (half) written window-ordered.
// ---------------------------------------------------------------------------
__global__ void __launch_bounds__(256)
projln_kernel(const __half* __restrict__ Ag, const __half* __restrict__ Bt,
              const float* __restrict__ bias, const float* __restrict__ x,
              const float* __restrict__ n2g, const float* __restrict__ n2b,
              float* __restrict__ y, __half* __restrict__ h2) {
    constexpr int BM = 64, BN = 192, BK = 32, STG = 3, K = 192;
    constexpr int STR = BK + 8;
    constexpr int AH = BM * STR;                // 2560
    constexpr int BH = BN * STR;                // 7680
    constexpr int STW = AH + BH;                // 10240 halves / stage

    extern __shared__ __align__(16) __half dynsm[];
    __shared__ float ssum[BM], ssq[BM];

    const int tid = threadIdx.x;
    const int w = tid >> 5, l = tid & 31;
    const int wm = w >> 2, wn = w & 3;

    if (tid < BM) { ssum[tid] = 0.f; ssq[tid] = 0.f; }

    const __half* Ab = Ag + (size_t)blockIdx.y * BM * K;
    const uint32_t smb = (uint32_t)__cvta_generic_to_shared(dynsm);

    const uint32_t a_off = (uint32_t)(((wm * 32 + (l & 15)) * STR + (l >> 4) * 8) * 2);
    const int n_off = (l & 7) + ((l >> 4) << 3);
    const int k_off = ((l >> 3) & 1) * 8;
    const uint32_t b_off = (uint32_t)((AH + (wn * 48 + n_off) * STR + k_off) * 2);

    float acc[2][6][4];
#pragma unroll
    for (int mt = 0; mt < 2; mt++)
#pragma unroll
        for (int nt = 0; nt < 6; nt++)
#pragma unroll
            for (int i = 0; i < 4; i++) acc[mt][nt][i] = 0.f;

    auto load = [&](int kc, int s) {
        uint32_t base = smb + (uint32_t)(s * STW) * 2u;
        {                                       // A: 64 rows x 4 chunks = 256
            int r = tid >> 2, c4 = tid & 3;
            cp_async16(base + (uint32_t)(r * STR + c4 * 8) * 2u,
                       Ab + (size_t)r * K + kc * BK + c4 * 8);
        }
#pragma unroll
        for (int it = 0; it < 3; it++) {        // B: 192 rows x 4 chunks = 768
            int i = tid + it * 256;
            int r = i >> 2, c4 = i & 3;
            cp_async16(base + (uint32_t)(AH + r * STR + c4 * 8) * 2u,
                       Bt + (size_t)r * K + kc * BK + c4 * 8);
        }
    };

    auto compute = [&](int s) {
        uint32_t stage = smb + (uint32_t)(s * STW) * 2u;
#pragma unroll
        for (int ks = 0; ks < 2; ks++) {
            uint32_t af[2][4], bf[6][2];
#pragma unroll
            for (int mt = 0; mt < 2; mt++)
                ldsm4(af[mt], stage + a_off + (uint32_t)((mt * 16 * STR + ks * 16) * 2));
#pragma unroll
            for (int ntp = 0; ntp < 3; ntp++) {
                uint32_t t4[4];
                ldsm4(t4, stage + b_off + (uint32_t)((ntp * 16 * STR + ks * 16) * 2));
                bf[ntp * 2 + 0][0] = t4[0]; bf[ntp * 2 + 0][1] = t4[1];
                bf[ntp * 2 + 1][0] = t4[2]; bf[ntp * 2 + 1][1] = t4[3];
            }
#pragma unroll
            for (int mt = 0; mt < 2; mt++)
#pragma unroll
                for (int nt = 0; nt < 6; nt++)
                    mma_f16(acc[mt][nt], af[mt], bf[nt]);
        }
    };

    const int CHUNKS = K / BK;                  // 6
#pragma unroll
    for (int s = 0; s < STG - 1; s++) {
        load(s, s);
        asm volatile("cp.async.commit_group;\n" ::: "memory");
    }
    for (int c = 0; c < CHUNKS; c++) {
        asm volatile("cp.async.wait_group %0;\n" :: "n"(STG - 2) : "memory");
        __syncthreads();
        if (c + STG - 1 < CHUNKS) load(c + STG - 1, (c + STG - 1) % STG);
        asm volatile("cp.async.commit_group;\n" ::: "memory");
        compute(c % STG);
        __syncthreads();
    }

    // ---- epilogue: y = x[orig] + (acc+bias); block-wide per-row LN ----
    const int lrow0 = wm * 32 + (l >> 2);       // local row base
    const int col0  = wn * 48 + 2 * (l & 3);
#pragma unroll
    for (int mt = 0; mt < 2; mt++) {
#pragma unroll
        for (int h = 0; h < 2; h++) {
            int lrow = lrow0 + mt * 16 + h * 8;
            int grow = blockIdx.y * BM + lrow;
            int orow = win2orig(grow);
            float ps = 0.f, pq = 0.f;
#pragma unroll
            for (int nt = 0; nt < 6; nt++) {
                int col = col0 + nt * 8;
                float v0 = acc[mt][nt][h * 2 + 0] + bias[col]
                         + x[(size_t)orow * BN + col];
                float v1 = acc[mt][nt][h * 2 + 1] + bias[col + 1]
                         + x[(size_t)orow * BN + col + 1];
                acc[mt][nt][h * 2 + 0] = v0;
                acc[mt][nt][h * 2 + 1] = v1;
                *(float2*)(y + (size_t)grow * BN + col) = make_float2(v0, v1);
                ps += v0 + v1;
                pq += v0 * v0 + v1 * v1;
            }
            atomicAdd(&ssum[lrow], ps);
            atomicAdd(&ssq[lrow], pq);
        }
    }
    __syncthreads();
#pragma unroll
    for (int mt = 0; mt < 2; mt++) {
#pragma unroll
        for (int h = 0; h < 2; h++) {
            int lrow = lrow0 + mt * 16 + h * 8;
            int grow = blockIdx.y * BM + lrow;
            float mean = ssum[lrow] * (1.f / BN);
            float var  = ssq[lrow] * (1.f / BN) - mean * mean;
            float inv  = rsqrtf(var + 1e-5f);
#pragma unroll
            for (int nt = 0; nt < 6; nt++) {
                int col = col0 + nt * 8;
                float v0 = (acc[mt][nt][h * 2 + 0] - mean) * inv * n2g[col] + n2b[col];
                float v1 = (acc[mt][nt][h * 2 + 1] - mean) * inv * n2g[col + 1] + n2b[col + 1];
                *(__half2*)(h2 + (size_t)grow * BN + col) = __floats2half2_rn(v0, v1);
            }
        }
    }
}

// ---------------------------------------------------------------------------
extern "C" void kernel_launch(void* const* d_in, const int* in_sizes, int n_in,
                              void* d_out, int out_size) {
    const float* x       = (const float*)d_in[0];
    const float* qg      = (const float*)d_in[1];
    const float* n1g     = (const float*)d_in[2];
    const float* n1b     = (const float*)d_in[3];
    const float* qkv_w   = (const float*)d_in[4];
    const float* qkv_b   = (const float*)d_in[5];
    const float* rpb     = (const float*)d_in[6];
    const float* proj_w  = (const float*)d_in[7];
    const float* proj_b  = (const float*)d_in[8];
    const float* n2g     = (const float*)d_in[9];
    const float* n2b     = (const float*)d_in[10];
    const float* fc1_w   = (const float*)d_in[11];
    const float* fc1_b   = (const float*)d_in[12];
    const float* fc2_w   = (const float*)d_in[13];
    const float* fc2_b   = (const float*)d_in[14];
    float* out = (float*)d_out;

    __half *hwin, *kvh, *owh, *h2h, *a1h, *wt;
    float *yb;
    cudaGetSymbolAddress((void**)&hwin, g_hwin_h);
    cudaGetSymbolAddress((void**)&kvh,  g_kv_h);
    cudaGetSymbolAddress((void**)&owh,  g_ow_h);
    cudaGetSymbolAddress((void**)&yb,   g_y);
    cudaGetSymbolAddress((void**)&h2h,  g_h2_h);
    cudaGetSymbolAddress((void**)&a1h,  g_a1_h);
    cudaGetSymbolAddress((void**)&wt,   g_wt);

    __half* qkv_t = wt;
    __half* proj_t = wt + 73728;
    __half* fc1_t = wt + 110592;
    __half* fc2_t = wt + 258048;

    // weight conversion (tiny)
    wconv_kernel<<<dim3(384 / 32, 192 / 32), dim3(32, 8)>>>(qkv_w, qkv_t, CH, 384);
    wconv_kernel<<<dim3(192 / 32, 192 / 32), dim3(32, 8)>>>(proj_w, proj_t, CH, CH);
    wconv_kernel<<<dim3(768 / 32, 192 / 32), dim3(32, 8)>>>(fc1_w, fc1_t, CH, HIDDEN);
    wconv_kernel<<<dim3(192 / 32, 768 / 32), dim3(32, 8)>>>(fc2_w, fc2_t, HIDDEN, CH);

    // 1. LN1 + window partition (half out)
    ln1_win_kernel<<<TOKENS / 8, 256>>>(x, n1g, n1b, hwin);

    // 2. KV GEMM -> half kv
    hgemm_kernel<3><<<dim3(384 / 64, TOKENS / 128), 256>>>(
        hwin, qkv_t, qkv_b, nullptr, kvh, 384, CH);

    // 3. attention (half in/out)
    attn_kernel<<<dim3(NHEADS, NWIN), WN_TOK>>>(kvh, qg, rpb, owh);

    // 4. proj + residual + LN2 fused (window-ordered y, h2)
    {
        constexpr int STW = (64 * 40 + 192 * 40);      // halves per stage
        constexpr int SMEM = STW * 3 * 2;              // bytes
        static bool attr_set = false;
        if (!attr_set) {
            cudaFuncSetAttribute(projln_kernel,
                cudaFuncAttributeMaxDynamicSharedMemorySize, SMEM);
            attr_set = true;
        }
        projln_kernel<<<dim3(1, TOKENS / 64), 256, SMEM>>>(
            owh, proj_t, proj_b, x, n2g, n2b, yb, h2h);
    }

    // 5. fc1 + GELU -> half a1
    hgemm_kernel<1><<<dim3(HIDDEN / 64, TOKENS / 128), 256>>>(
        h2h, fc1_t, fc1_b, nullptr, a1h, HIDDEN, CH);

    // 6. fc2 + residual(y) -> out (window-reverse store)
    hgemm_kernel<2><<<dim3(CH / 64, TOKENS / 128), 256>>>(
        a1h, fc2_t, fc2_b, yb, out, CH, HIDDEN);
}

// round 11
// speedup vs baseline: 1.4327x; 1.4327x over previous
#include <cuda_runtime.h>
#include <cuda_fp16.h>
#include <math.h>
#include <stdint.h>

// ---------------------------------------------------------------------------
// GCViT block, R11 (= R9 resubmit): tensor-core attention (f16 mma, fp32
// accum), 128x128 GEMM tiles for kv/fc1, proj+res+LN2 fused, window-reverse
// folded into fc2 store.
// Shapes: B=32 H=W=64 C=192 NH=6 hd=32 WS=8 N=64 hidden=768
// ---------------------------------------------------------------------------

#define TOKENS   131072
#define CH       192
#define HIDDEN   768
#define NWIN     2048
#define NHEADS   6
#define HD       32

__device__ __half g_hwin_h[TOKENS * CH];          // LN1 out, window order
__device__ __half g_kv_h [TOKENS * 2 * CH];       // KV, window order
__device__ __half g_ow_h [TOKENS * CH];           // attn out, window order
__device__ float  g_y    [TOKENS * CH];           // residual-1, WINDOW order
__device__ __half g_h2_h [TOKENS * CH];           // LN2 out, WINDOW order
__device__ __half g_a1_h [TOKENS * HIDDEN];       // fc1 act, window order
__device__ __half g_wt[73728 + 36864 + 147456 + 147456];

__device__ __forceinline__ int win2orig(int w) {
    int bi = w >> 12, rem = w & 4095;
    int win = rem >> 6, pos = rem & 63;
    return (bi << 12) + ((((win >> 3) << 3) + (pos >> 3)) << 6)
         + ((win & 7) << 3) + (pos & 7);
}

__device__ __forceinline__ float warp_sum(float v) {
#pragma unroll
    for (int o = 16; o; o >>= 1) v += __shfl_xor_sync(0xffffffffu, v, o);
    return v;
}

__device__ __forceinline__ uint32_t pack_half2(float a, float b) {
    __half2 hv = __floats2half2_rn(a, b);
    return *(uint32_t*)&hv;
}

__device__ __forceinline__ void cp_async16(uint32_t d, const void* s) {
    asm volatile("cp.async.cg.shared.global [%0], [%1], 16;\n" :: "r"(d), "l"(s));
}
__device__ __forceinline__ void ldsm4(uint32_t* r, uint32_t addr) {
    asm volatile("ldmatrix.sync.aligned.m8n8.x4.shared.b16 {%0,%1,%2,%3}, [%4];\n"
                 : "=r"(r[0]), "=r"(r[1]), "=r"(r[2]), "=r"(r[3]) : "r"(addr));
}
__device__ __forceinline__ void ldsm4t(uint32_t* r, uint32_t addr) {
    asm volatile("ldmatrix.sync.aligned.m8n8.x4.trans.shared.b16 {%0,%1,%2,%3}, [%4];\n"
                 : "=r"(r[0]), "=r"(r[1]), "=r"(r[2]), "=r"(r[3]) : "r"(addr));
}
__device__ __forceinline__ void mma_f16(float* c, const uint32_t* a, const uint32_t* b) {
    asm volatile(
        "mma.sync.aligned.m16n8k16.row.col.f32.f16.f16.f32 "
        "{%0,%1,%2,%3}, {%4,%5,%6,%7}, {%8,%9}, {%0,%1,%2,%3};\n"
        : "+f"(c[0]), "+f"(c[1]), "+f"(c[2]), "+f"(c[3])
        : "r"(a[0]), "r"(a[1]), "r"(a[2]), "r"(a[3]), "r"(b[0]), "r"(b[1]));
}

// W[K][N] f32 -> Wt[N][K] half
__global__ void wconv_kernel(const float* __restrict__ W, __half* __restrict__ Wt,
                             int K, int N) {
    __shared__ float t[32][33];
    int k0 = blockIdx.y * 32, n0 = blockIdx.x * 32;
    int tx = threadIdx.x, ty = threadIdx.y;
#pragma unroll
    for (int i = 0; i < 32; i += 8)
        t[ty + i][tx] = W[(size_t)(k0 + ty + i) * N + n0 + tx];
    __syncthreads();
#pragma unroll
    for (int i = 0; i < 32; i += 8)
        Wt[(size_t)(n0 + ty + i) * K + k0 + tx] = __float2half(t[tx][ty + i]);
}

__global__ void ln1_win_kernel(const float* __restrict__ x,
                               const float* __restrict__ g,
                               const float* __restrict__ b,
                               __half* __restrict__ hw) {
    int tok  = (blockIdx.x * blockDim.x + threadIdx.x) >> 5;
    int lane = threadIdx.x & 31;
    const float* xr = x + (size_t)tok * CH;
    float v[6], s = 0.f, s2 = 0.f;
#pragma unroll
    for (int j = 0; j < 6; j++) {
        float t = xr[lane + 32 * j];
        v[j] = t; s += t; s2 += t * t;
    }
    s = warp_sum(s); s2 = warp_sum(s2);
    float mean = s * (1.f / CH);
    float var  = s2 * (1.f / CH) - mean * mean;
    float inv  = rsqrtf(var + 1e-5f);
    int bi = tok >> 12;
    int hh = (tok >> 6) & 63;
    int ww = tok & 63;
    size_t dst = ((size_t)(bi * 64 + ((hh >> 3) << 3) + (ww >> 3)) * 64
                  + ((hh & 7) << 3) + (ww & 7)) * CH;
#pragma unroll
    for (int j = 0; j < 6; j++) {
        int c = lane + 32 * j;
        hw[dst + c] = __float2half((v[j] - mean) * inv * g[c] + b[c]);
    }
}

// ---------------------------------------------------------------------------
// Tensor-core attention. block = 1 window (128 thr, 4 warps); 6 heads looped.
// Warp w owns query rows [w*16, w*16+16).
// ---------------------------------------------------------------------------
#define KVSTR 392     // halves per kv smem row (384 + 8 pad)
#define QSTR  200     // halves per q smem row (192 + 8 pad)

__global__ void __launch_bounds__(128)
attn_tc_kernel(const __half* __restrict__ kv, const float* __restrict__ qg,
               const float* __restrict__ rpb, __half* __restrict__ ow) {
    extern __shared__ __align__(16) unsigned char smraw[];
    __half* kvs = (__half*)smraw;                 // [64][KVSTR]
    __half* qs  = kvs + 64 * KVSTR;               // [64][QSTR]
    float*  bsh = (float*)(qs + 64 * QSTR);       // [6][225]

    const int wb  = blockIdx.x;
    const int tid = threadIdx.x, w = tid >> 5, l = tid & 31;
    const int bimg = wb >> 6;

    // stage K|V tile (64 x 384 half) via cp.async
    const uint32_t kvs_b = (uint32_t)__cvta_generic_to_shared(kvs);
    const uint32_t qs_b  = (uint32_t)__cvta_generic_to_shared(qs);
    const __half* kvg = kv + (size_t)wb * 64 * 384;
#pragma unroll
    for (int it = 0; it < 24; it++) {
        int i = tid + it * 128;
        int r = i / 48, c = i % 48;
        cp_async16(kvs_b + (uint32_t)(r * KVSTR + c * 8) * 2u,
                   kvg + (size_t)r * 384 + c * 8);
    }
    asm volatile("cp.async.commit_group;\n" ::: "memory");

    // stage Q (f32 -> half, pre-scaled)
    const float2* qsrc = (const float2*)(qg + (size_t)bimg * 64 * 192);
#pragma unroll
    for (int it = 0; it < 48; it++) {
        int i = tid + it * 128;            // float2 units
        int r = i / 96, c2 = i % 96;
        float2 v = qsrc[(size_t)r * 96 + c2];
        *(__half2*)&qs[r * QSTR + c2 * 2] =
            __floats2half2_rn(v.x * 0.17677669529663687f, v.y * 0.17677669529663687f);
    }
    for (int i = tid; i < 6 * 225; i += 128)
        bsh[i] = rpb[(i % 225) * NHEADS + (i / 225)];

    asm volatile("cp.async.wait_group 0;\n" ::: "memory");
    __syncthreads();

    const int r0 = w * 16 + (l >> 2);     // lower query row
    const int c0 = 2 * (l & 3);

    for (int h = 0; h < NHEADS; h++) {
        // ---- S = Q K^T + bias : acc init with bias ----
        float sacc[8][4];
        const float* bh = bsh + h * 225;
#pragma unroll
        for (int nt = 0; nt < 8; nt++) {
#pragma unroll
            for (int i = 0; i < 4; i++) {
                int qr = r0 + ((i >= 2) ? 8 : 0);
                int kc = nt * 8 + c0 + (i & 1);
                sacc[nt][i] = bh[((qr >> 3) - (kc >> 3) + 7) * 15
                               + ((qr & 7) - (kc & 7) + 7)];
            }
        }
#pragma unroll
        for (int ks = 0; ks < 2; ks++) {
            uint32_t aq[4];
            ldsm4(aq, qs_b + (uint32_t)((w * 16 + (l & 15)) * QSTR
                                        + h * 32 + ks * 16 + (l >> 4) * 8) * 2u);
#pragma unroll
            for (int ntp = 0; ntp < 4; ntp++) {
                uint32_t t4[4];
                ldsm4(t4, kvs_b + (uint32_t)((ntp * 16 + (l & 7) + ((l >> 4) << 3)) * KVSTR
                                             + h * 32 + ks * 16 + (((l >> 3) & 1) << 3)) * 2u);
                uint32_t b0[2] = {t4[0], t4[1]}, b1[2] = {t4[2], t4[3]};
                mma_f16(sacc[ntp * 2 + 0], aq, b0);
                mma_f16(sacc[ntp * 2 + 1], aq, b1);
            }
        }

        // ---- softmax over 64 cols (rows r0 and r0+8) ----
        float mx0 = -1e30f, mx1 = -1e30f;
#pragma unroll
        for (int nt = 0; nt < 8; nt++) {
            mx0 = fmaxf(mx0, fmaxf(sacc[nt][0], sacc[nt][1]));
            mx1 = fmaxf(mx1, fmaxf(sacc[nt][2], sacc[nt][3]));
        }
#pragma unroll
        for (int o = 1; o <= 2; o <<= 1) {
            mx0 = fmaxf(mx0, __shfl_xor_sync(0xffffffffu, mx0, o));
            mx1 = fmaxf(mx1, __shfl_xor_sync(0xffffffffu, mx1, o));
        }
        float s0 = 0.f, s1 = 0.f;
#pragma unroll
        for (int nt = 0; nt < 8; nt++) {
            sacc[nt][0] = expf(sacc[nt][0] - mx0);
            sacc[nt][1] = expf(sacc[nt][1] - mx0);
            sacc[nt][2] = expf(sacc[nt][2] - mx1);
            sacc[nt][3] = expf(sacc[nt][3] - mx1);
            s0 += sacc[nt][0] + sacc[nt][1];
            s1 += sacc[nt][2] + sacc[nt][3];
        }
#pragma unroll
        for (int o = 1; o <= 2; o <<= 1) {
            s0 += __shfl_xor_sync(0xffffffffu, s0, o);
            s1 += __shfl_xor_sync(0xffffffffu, s1, o);
        }

        // ---- O = P V (P reused as A-fragments) ----
        float oacc[4][4];
#pragma unroll
        for (int nt = 0; nt < 4; nt++)
#pragma unroll
            for (int i = 0; i < 4; i++) oacc[nt][i] = 0.f;

#pragma unroll
        for (int kk = 0; kk < 4; kk++) {    // m-blocks of 16 keys
            uint32_t pa[4];
            pa[0] = pack_half2(sacc[2*kk][0],   sacc[2*kk][1]);
            pa[1] = pack_half2(sacc[2*kk][2],   sacc[2*kk][3]);
            pa[2] = pack_half2(sacc[2*kk+1][0], sacc[2*kk+1][1]);
            pa[3] = pack_half2(sacc[2*kk+1][2], sacc[2*kk+1][3]);
#pragma unroll
            for (int dh = 0; dh < 2; dh++) {  // d-halves of 16
                uint32_t t4[4];
                ldsm4t(t4, kvs_b + (uint32_t)((kk * 16 + (l & 15)) * KVSTR
                                              + 192 + h * 32 + dh * 16 + ((l & 16) ? 8 : 0)) * 2u);
                uint32_t b0[2] = {t4[0], t4[1]}, b1[2] = {t4[2], t4[3]};
                mma_f16(oacc[2 * dh + 0], pa, b0);
                mma_f16(oacc[2 * dh + 1], pa, b1);
            }
        }

        // ---- store O (normalized) ----
        const float i0 = 1.f / s0, i1 = 1.f / s1;
        __half* od = ow + ((size_t)wb * 64) * CH + h * 32;
#pragma unroll
        for (int nt = 0; nt < 4; nt++) {
            int col = nt * 8 + c0;
            *(__half2*)&od[(size_t)r0 * CH + col] =
                __floats2half2_rn(oacc[nt][0] * i0, oacc[nt][1] * i0);
            *(__half2*)&od[(size_t)(r0 + 8) * CH + col] =
                __floats2half2_rn(oacc[nt][2] * i1, oacc[nt][3] * i1);
        }
    }
}

// ---------------------------------------------------------------------------
// 256-thread f16 GEMM, BM=128 BN=128 BK=32, warp tile 64x32 (2x4 warps).
// EPI: 1=bias+GELU->half  3=bias->half
// ---------------------------------------------------------------------------
template<int EPI>
__global__ void __launch_bounds__(256)
hgemm128_kernel(const __half* __restrict__ Ag, const __half* __restrict__ Bt,
                const float* __restrict__ bias, __half* __restrict__ Cg,
                int N, int K) {
    constexpr int BM = 128, BN = 128, BK = 32, STG = 3;
    constexpr int STR = BK + 8;
    constexpr int AH = BM * STR;                // 5120
    constexpr int BH = BN * STR;                // 5120
    constexpr int STW = AH + BH;                // 10240 halves

    extern __shared__ __align__(16) __half sm[];

    const int tid = threadIdx.x;
    const int w = tid >> 5, l = tid & 31;
    const int wm = w >> 2, wn = w & 3;

    const __half* Ab = Ag + (size_t)blockIdx.y * BM * K;
    const __half* Bb = Bt + (size_t)blockIdx.x * BN * K;
    const uint32_t smb = (uint32_t)__cvta_generic_to_shared(sm);

    const uint32_t a_off = (uint32_t)(((wm * 64 + (l & 15)) * STR + (l >> 4) * 8) * 2);
    const int n_off = (l & 7) + ((l >> 4) << 3);
    const int k_off = ((l >> 3) & 1) * 8;
    const uint32_t b_off = (uint32_t)((AH + (wn * 32 + n_off) * STR + k_off) * 2);

    float acc[4][4][4];
#pragma unroll
    for (int mt = 0; mt < 4; mt++)
#pragma unroll
        for (int nt = 0; nt < 4; nt++)
#pragma unroll
            for (int i = 0; i < 4; i++) acc[mt][nt][i] = 0.f;

    auto load = [&](int kc, int s) {
        uint32_t base = smb + (uint32_t)(s * STW) * 2u;
#pragma unroll
        for (int it = 0; it < 2; it++) {
            int i = tid + it * 256;
            int r = i >> 2, c4 = i & 3;
            cp_async16(base + (uint32_t)(r * STR + c4 * 8) * 2u,
                       Ab + (size_t)r * K + kc * BK + c4 * 8);
        }
#pragma unroll
        for (int it = 0; it < 2; it++) {
            int i = tid + it * 256;
            int r = i >> 2, c4 = i & 3;
            cp_async16(base + (uint32_t)(AH + r * STR + c4 * 8) * 2u,
                       Bb + (size_t)r * K + kc * BK + c4 * 8);
        }
    };

    auto compute = [&](int s) {
        uint32_t stage = smb + (uint32_t)(s * STW) * 2u;
#pragma unroll
        for (int ks = 0; ks < 2; ks++) {
            uint32_t af[4][4], bf[4][2];
#pragma unroll
            for (int mt = 0; mt < 4; mt++)
                ldsm4(af[mt], stage + a_off + (uint32_t)((mt * 16 * STR + ks * 16) * 2));
#pragma unroll
            for (int ntp = 0; ntp < 2; ntp++) {
                uint32_t t4[4];
                ldsm4(t4, stage + b_off + (uint32_t)((ntp * 16 * STR + ks * 16) * 2));
                bf[ntp * 2 + 0][0] = t4[0]; bf[ntp * 2 + 0][1] = t4[1];
                bf[ntp * 2 + 1][0] = t4[2]; bf[ntp * 2 + 1][1] = t4[3];
            }
#pragma unroll
            for (int mt = 0; mt < 4; mt++)
#pragma unroll
                for (int nt = 0; nt < 4; nt++)
                    mma_f16(acc[mt][nt], af[mt], bf[nt]);
        }
    };

    const int CHUNKS = K / BK;
#pragma unroll
    for (int s = 0; s < STG - 1; s++) {
        load(s, s);
        asm volatile("cp.async.commit_group;\n" ::: "memory");
    }
    for (int c = 0; c < CHUNKS; c++) {
        asm volatile("cp.async.wait_group %0;\n" :: "n"(STG - 2) : "memory");
        __syncthreads();
        if (c + STG - 1 < CHUNKS) load(c + STG - 1, (c + STG - 1) % STG);
        asm volatile("cp.async.commit_group;\n" ::: "memory");
        compute(c % STG);
        __syncthreads();
    }

    const int row0 = blockIdx.y * BM + wm * 64 + (l >> 2);
    const int col0 = blockIdx.x * BN + wn * 32 + 2 * (l & 3);
#pragma unroll
    for (int mt = 0; mt < 4; mt++) {
#pragma unroll
        for (int h = 0; h < 2; h++) {
            size_t row = (size_t)row0 + mt * 16 + h * 8;
#pragma unroll
            for (int nt = 0; nt < 4; nt++) {
                int col = col0 + nt * 8;
                float v0 = acc[mt][nt][h * 2 + 0] + bias[col];
                float v1 = acc[mt][nt][h * 2 + 1] + bias[col + 1];
                if (EPI == 1) {
                    v0 = 0.5f * v0 * (1.0f + erff(v0 * 0.70710678118654752f));
                    v1 = 0.5f * v1 * (1.0f + erff(v1 * 0.70710678118654752f));
                }
                *(__half2*)(Cg + row * N + col) = __floats2half2_rn(v0, v1);
            }
        }
    }
}

// ---------------------------------------------------------------------------
// fc2: 128-thread GEMM BM=128 BN=64, +residual(y), window-reverse store.
// ---------------------------------------------------------------------------
__global__ void __launch_bounds__(128)
fc2_kernel(const __half* __restrict__ Ag, const __half* __restrict__ Bt,
           const float* __restrict__ bias, const float* __restrict__ res,
           float* __restrict__ Cg, int N, int K) {
    constexpr int BM = 128, BN = 64, BK = 32, STG = 3;
    constexpr int STR = BK + 8;
    constexpr int AH = BM * STR;
    constexpr int STW = AH + BN * STR;

    __shared__ __half sm[STW * STG];

    const int tid = threadIdx.x;
    const int w = tid >> 5, l = tid & 31;
    const int wm = w >> 1, wn = w & 1;

    const __half* Ab = Ag + (size_t)blockIdx.y * BM * K;
    const __half* Bb = Bt + (size_t)blockIdx.x * BN * K;
    const uint32_t smb = (uint32_t)__cvta_generic_to_shared(sm);

    const uint32_t a_off = (uint32_t)(((wm * 64 + (l & 15)) * STR + (l >> 4) * 8) * 2);
    const int n_off = (l & 7) + ((l >> 4) << 3);
    const int k_off = ((l >> 3) & 1) * 8;
    const uint32_t b_off = (uint32_t)((AH + (wn * 32 + n_off) * STR + k_off) * 2);

    float acc[4][4][4];
#pragma unroll
    for (int mt = 0; mt < 4; mt++)
#pragma unroll
        for (int nt = 0; nt < 4; nt++)
#pragma unroll
            for (int i = 0; i < 4; i++) acc[mt][nt][i] = 0.f;

    auto load = [&](int kc, int s) {
        uint32_t base = smb + (uint32_t)(s * STW) * 2u;
#pragma unroll
        for (int it = 0; it < 4; it++) {
            int i = tid + it * 128;
            int r = i >> 2, c4 = i & 3;
            cp_async16(base + (uint32_t)(r * STR + c4 * 8) * 2u,
                       Ab + (size_t)r * K + kc * BK + c4 * 8);
        }
#pragma unroll
        for (int it = 0; it < 2; it++) {
            int i = tid + it * 128;
            int r = i >> 2, c4 = i & 3;
            cp_async16(base + (uint32_t)(AH + r * STR + c4 * 8) * 2u,
                       Bb + (size_t)r * K + kc * BK + c4 * 8);
        }
    };

    auto compute = [&](int s) {
        uint32_t stage = smb + (uint32_t)(s * STW) * 2u;
#pragma unroll
        for (int ks = 0; ks < 2; ks++) {
            uint32_t af[4][4], bf[4][2];
#pragma unroll
            for (int mt = 0; mt < 4; mt++)
                ldsm4(af[mt], stage + a_off + (uint32_t)((mt * 16 * STR + ks * 16) * 2));
#pragma unroll
            for (int ntp = 0; ntp < 2; ntp++) {
                uint32_t t4[4];
                ldsm4(t4, stage + b_off + (uint32_t)((ntp * 16 * STR + ks * 16) * 2));
                bf[ntp * 2 + 0][0] = t4[0]; bf[ntp * 2 + 0][1] = t4[1];
                bf[ntp * 2 + 1][0] = t4[2]; bf[ntp * 2 + 1][1] = t4[3];
            }
#pragma unroll
            for (int mt = 0; mt < 4; mt++)
#pragma unroll
                for (int nt = 0; nt < 4; nt++)
                    mma_f16(acc[mt][nt], af[mt], bf[nt]);
        }
    };

    const int CHUNKS = K / BK;
#pragma unroll
    for (int s = 0; s < STG - 1; s++) {
        load(s, s);
        asm volatile("cp.async.commit_group;\n" ::: "memory");
    }
    for (int c = 0; c < CHUNKS; c++) {
        asm volatile("cp.async.wait_group %0;\n" :: "n"(STG - 2) : "memory");
        __syncthreads();
        if (c + STG - 1 < CHUNKS) load(c + STG - 1, (c + STG - 1) % STG);
        asm volatile("cp.async.commit_group;\n" ::: "memory");
        compute(c % STG);
        __syncthreads();
    }

    const int row0 = blockIdx.y * BM + wm * 64 + (l >> 2);
    const int col0 = blockIdx.x * BN + wn * 32 + 2 * (l & 3);
#pragma unroll
    for (int mt = 0; mt < 4; mt++) {
#pragma unroll
        for (int h = 0; h < 2; h++) {
            int row = row0 + mt * 16 + h * 8;
            int orow = win2orig(row);
#pragma unroll
            for (int nt = 0; nt < 4; nt++) {
                int col = col0 + nt * 8;
                float v0 = acc[mt][nt][h * 2 + 0] + bias[col] + res[(size_t)row * N + col];
                float v1 = acc[mt][nt][h * 2 + 1] + bias[col + 1] + res[(size_t)row * N + col + 1];
                *(float2*)(Cg + (size_t)orow * N + col) = make_float2(v0, v1);
            }
        }
    }
}

// ---------------------------------------------------------------------------
// Fused proj GEMM + residual + LN2 (window-ordered y, h2).
// ---------------------------------------------------------------------------
__global__ void __launch_bounds__(256)
projln_kernel(const __half* __restrict__ Ag, const __half* __restrict__ Bt,
              const float* __restrict__ bias, const float* __restrict__ x,
              const float* __restrict__ n2g, const float* __restrict__ n2b,
              float* __restrict__ y, __half* __restrict__ h2) {
    constexpr int BM = 64, BN = 192, BK = 32, STG = 3, K = 192;
    constexpr int STR = BK + 8;
    constexpr int AH = BM * STR;
    constexpr int STW = AH + BN * STR;

    extern __shared__ __align__(16) __half dynsm[];
    __shared__ float ssum[BM], ssq[BM];

    const int tid = threadIdx.x;
    const int w = tid >> 5, l = tid & 31;
    const int wm = w >> 2, wn = w & 3;

    if (tid < BM) { ssum[tid] = 0.f; ssq[tid] = 0.f; }

    const __half* Ab = Ag + (size_t)blockIdx.y * BM * K;
    const uint32_t smb = (uint32_t)__cvta_generic_to_shared(dynsm);

    const uint32_t a_off = (uint32_t)(((wm * 32 + (l & 15)) * STR + (l >> 4) * 8) * 2);
    const int n_off = (l & 7) + ((l >> 4) << 3);
    const int k_off = ((l >> 3) & 1) * 8;
    const uint32_t b_off = (uint32_t)((AH + (wn * 48 + n_off) * STR + k_off) * 2);

    float acc[2][6][4];
#pragma unroll
    for (int mt = 0; mt < 2; mt++)
#pragma unroll
        for (int nt = 0; nt < 6; nt++)
#pragma unroll
            for (int i = 0; i < 4; i++) acc[mt][nt][i] = 0.f;

    auto load = [&](int kc, int s) {
        uint32_t base = smb + (uint32_t)(s * STW) * 2u;
        {
            int r = tid >> 2, c4 = tid & 3;
            cp_async16(base + (uint32_t)(r * STR + c4 * 8) * 2u,
                       Ab + (size_t)r * K + kc * BK + c4 * 8);
        }
#pragma unroll
        for (int it = 0; it < 3; it++) {
            int i = tid + it * 256;
            int r = i >> 2, c4 = i & 3;
            cp_async16(base + (uint32_t)(AH + r * STR + c4 * 8) * 2u,
                       Bt + (size_t)r * K + kc * BK + c4 * 8);
        }
    };

    auto compute = [&](int s) {
        uint32_t stage = smb + (uint32_t)(s * STW) * 2u;
#pragma unroll
        for (int ks = 0; ks < 2; ks++) {
            uint32_t af[2][4], bf[6][2];
#pragma unroll
            for (int mt = 0; mt < 2; mt++)
                ldsm4(af[mt], stage + a_off + (uint32_t)((mt * 16 * STR + ks * 16) * 2));
#pragma unroll
            for (int ntp = 0; ntp < 3; ntp++) {
                uint32_t t4[4];
                ldsm4(t4, stage + b_off + (uint32_t)((ntp * 16 * STR + ks * 16) * 2));
                bf[ntp * 2 + 0][0] = t4[0]; bf[ntp * 2 + 0][1] = t4[1];
                bf[ntp * 2 + 1][0] = t4[2]; bf[ntp * 2 + 1][1] = t4[3];
            }
#pragma unroll
            for (int mt = 0; mt < 2; mt++)
#pragma unroll
                for (int nt = 0; nt < 6; nt++)
                    mma_f16(acc[mt][nt], af[mt], bf[nt]);
        }
    };

    const int CHUNKS = K / BK;
#pragma unroll
    for (int s = 0; s < STG - 1; s++) {
        load(s, s);
        asm volatile("cp.async.commit_group;\n" ::: "memory");
    }
    for (int c = 0; c < CHUNKS; c++) {
        asm volatile("cp.async.wait_group %0;\n" :: "n"(STG - 2) : "memory");
        __syncthreads();
        if (c + STG - 1 < CHUNKS) load(c + STG - 1, (c + STG - 1) % STG);
        asm volatile("cp.async.commit_group;\n" ::: "memory");
        compute(c % STG);
        __syncthreads();
    }

    const int lrow0 = wm * 32 + (l >> 2);
    const int col0  = wn * 48 + 2 * (l & 3);
#pragma unroll
    for (int mt = 0; mt < 2; mt++) {
#pragma unroll
        for (int h = 0; h < 2; h++) {
            int lrow = lrow0 + mt * 16 + h * 8;
            int grow = blockIdx.y * BM + lrow;
            int orow = win2orig(grow);
            float ps = 0.f, pq = 0.f;
#pragma unroll
            for (int nt = 0; nt < 6; nt++) {
                int col = col0 + nt * 8;
                float v0 = acc[mt][nt][h * 2 + 0] + bias[col]
                         + x[(size_t)orow * BN + col];
                float v1 = acc[mt][nt][h * 2 + 1] + bias[col + 1]
                         + x[(size_t)orow * BN + col + 1];
                acc[mt][nt][h * 2 + 0] = v0;
                acc[mt][nt][h * 2 + 1] = v1;
                *(float2*)(y + (size_t)grow * BN + col) = make_float2(v0, v1);
                ps += v0 + v1;
                pq += v0 * v0 + v1 * v1;
            }
            ps += __shfl_xor_sync(0xffffffffu, ps, 1);
            ps += __shfl_xor_sync(0xffffffffu, ps, 2);
            pq += __shfl_xor_sync(0xffffffffu, pq, 1);
            pq += __shfl_xor_sync(0xffffffffu, pq, 2);
            if ((l & 3) == 0) {
                atomicAdd(&ssum[lrow], ps);
                atomicAdd(&ssq[lrow], pq);
            }
        }
    }
    __syncthreads();
#pragma unroll
    for (int mt = 0; mt < 2; mt++) {
#pragma unroll
        for (int h = 0; h < 2; h++) {
            int lrow = lrow0 + mt * 16 + h * 8;
            int grow = blockIdx.y * BM + lrow;
            float mean = ssum[lrow] * (1.f / BN);
            float var  = ssq[lrow] * (1.f / BN) - mean * mean;
            float inv  = rsqrtf(var + 1e-5f);
#pragma unroll
            for (int nt = 0; nt < 6; nt++) {
                int col = col0 + nt * 8;
                float v0 = (acc[mt][nt][h * 2 + 0] - mean) * inv * n2g[col] + n2b[col];
                float v1 = (acc[mt][nt][h * 2 + 1] - mean) * inv * n2g[col + 1] + n2b[col + 1];
                *(__half2*)(h2 + (size_t)grow * BN + col) = __floats2half2_rn(v0, v1);
            }
        }
    }
}

// ---------------------------------------------------------------------------
extern "C" void kernel_launch(void* const* d_in, const int* in_sizes, int n_in,
                              void* d_out, int out_size) {
    const float* x       = (const float*)d_in[0];
    const float* qg      = (const float*)d_in[1];
    const float* n1g     = (const float*)d_in[2];
    const float* n1b     = (const float*)d_in[3];
    const float* qkv_w   = (const float*)d_in[4];
    const float* qkv_b   = (const float*)d_in[5];
    const float* rpb     = (const float*)d_in[6];
    const float* proj_w  = (const float*)d_in[7];
    const float* proj_b  = (const float*)d_in[8];
    const float* n2g     = (const float*)d_in[9];
    const float* n2b     = (const float*)d_in[10];
    const float* fc1_w   = (const float*)d_in[11];
    const float* fc1_b   = (const float*)d_in[12];
    const float* fc2_w   = (const float*)d_in[13];
    const float* fc2_b   = (const float*)d_in[14];
    float* out = (float*)d_out;

    __half *hwin, *kvh, *owh, *h2h, *a1h, *wt;
    float *yb;
    cudaGetSymbolAddress((void**)&hwin, g_hwin_h);
    cudaGetSymbolAddress((void**)&kvh,  g_kv_h);
    cudaGetSymbolAddress((void**)&owh,  g_ow_h);
    cudaGetSymbolAddress((void**)&yb,   g_y);
    cudaGetSymbolAddress((void**)&h2h,  g_h2_h);
    cudaGetSymbolAddress((void**)&a1h,  g_a1_h);
    cudaGetSymbolAddress((void**)&wt,   g_wt);

    __half* qkv_t = wt;
    __half* proj_t = wt + 73728;
    __half* fc1_t = wt + 110592;
    __half* fc2_t = wt + 258048;

    const int gemm128_smem = (128 * 40 + 128 * 40) * 3 * 2;            // 61440
    const int projln_smem  = (64 * 40 + 192 * 40) * 3 * 2;             // 61440
    const int attn_smem    = (64 * KVSTR + 64 * QSTR) * 2 + 6 * 225 * 4;
    cudaFuncSetAttribute(hgemm128_kernel<1>,
        cudaFuncAttributeMaxDynamicSharedMemorySize, gemm128_smem);
    cudaFuncSetAttribute(hgemm128_kernel<3>,
        cudaFuncAttributeMaxDynamicSharedMemorySize, gemm128_smem);
    cudaFuncSetAttribute(projln_kernel,
        cudaFuncAttributeMaxDynamicSharedMemorySize, projln_smem);
    cudaFuncSetAttribute(attn_tc_kernel,
        cudaFuncAttributeMaxDynamicSharedMemorySize, attn_smem);

    wconv_kernel<<<dim3(12, 6), dim3(32, 8)>>>(qkv_w, qkv_t, CH, 384);
    wconv_kernel<<<dim3(6, 6), dim3(32, 8)>>>(proj_w, proj_t, CH, CH);
    wconv_kernel<<<dim3(24, 6), dim3(32, 8)>>>(fc1_w, fc1_t, CH, HIDDEN);
    wconv_kernel<<<dim3(6, 24), dim3(32, 8)>>>(fc2_w, fc2_t, HIDDEN, CH);

    // 1. LN1 + window partition
    ln1_win_kernel<<<TOKENS / 8, 256>>>(x, n1g, n1b, hwin);

    // 2. KV GEMM -> half
    hgemm128_kernel<3><<<dim3(384 / 128, TOKENS / 128), 256, gemm128_smem>>>(
        hwin, qkv_t, qkv_b, kvh, 384, CH);

    // 3. tensor-core attention
    attn_tc_kernel<<<NWIN, 128, attn_smem>>>(kvh, qg, rpb, owh);

    // 4. proj + residual + LN2 fused
    projln_kernel<<<dim3(1, TOKENS / 64), 256, projln_smem>>>(
        owh, proj_t, proj_b, x, n2g, n2b, yb, h2h);

    // 5. fc1 + GELU
    hgemm128_kernel<1><<<dim3(HIDDEN / 128, TOKENS / 128), 256, gemm128_smem>>>(
        h2h, fc1_t, fc1_b, a1h, HIDDEN, CH);

    // 6. fc2 + residual -> out (window-reverse store)
    fc2_kernel<<<dim3(CH / 64, TOKENS / 128), 128>>>(
        a1h, fc2_t, fc2_b, yb, out, CH, HIDDEN);
}